// round 14
// baseline (speedup 1.0000x reference)
#include <cuda_runtime.h>
#include <cstdint>

// CSCFCLayer: out[b][n] = sum_{f<64} x[b][(n+f)%C] * kernel[(n+f)%C][n] + bias[n]
// B=128, C=N=8192, F=64, fp32.
//
// v14 = v11 (band-trimmed m16n8k8 tf32, grid 128, 1024 thr, 1 barrier, full unroll)
//      + free B column permutation: each 4-col group stored [c0, c2, c1, c3]
//        (uint4 y/z swap at fill, zero cost). Consequences:
//        - B operands pairwise adjacent -> 2x LDS.64 per step (was 4x LDS.32),
//        - acc cols 4tg..4tg+3 consecutive -> 2x STG.128 epilogue + float4 bias.

#define CDIM 8192
#define NDIM 8192
#define NT 64
#define THREADS 1024
#define ASTRIDE 132
#define BSTRIDE 72
#define A_FLOATS (128 * ASTRIDE)
#define SMEM_NEED ((A_FLOATS + 128 * BSTRIDE) * 4)

__device__ __forceinline__ uint32_t f2tf(float f) {
    uint32_t r;
    asm("cvt.rna.tf32.f32 %0, %1;" : "=r"(r) : "f"(f));
    return r;
}

__device__ __forceinline__ void mma_tf32(float* c,
                                         uint32_t a0, uint32_t a1,
                                         uint32_t a2, uint32_t a3,
                                         uint32_t b0, uint32_t b1) {
    asm volatile(
        "mma.sync.aligned.m16n8k8.row.col.f32.tf32.tf32.f32 "
        "{%0,%1,%2,%3}, {%4,%5,%6,%7}, {%8,%9}, {%0,%1,%2,%3};"
        : "+f"(c[0]), "+f"(c[1]), "+f"(c[2]), "+f"(c[3])
        : "r"(a0), "r"(a1), "r"(a2), "r"(a3), "r"(b0), "r"(b1));
}

extern "C" __global__ void __launch_bounds__(THREADS, 1)
cscfc_mma_kernel(const float* __restrict__ x,
                 const float* __restrict__ w,
                 const float* __restrict__ bias,
                 float* __restrict__ out)
{
    extern __shared__ float sm[];
    float* As = sm;               // [128 b][ASTRIDE] raw fp32 x window
    float* Bs = sm + A_FLOATS;    // [128 k][BSTRIDE] banded tf32 weights, [k][perm(n)]

    const int tid  = threadIdx.x;
    const int lane = tid & 31;
    const int wid  = tid >> 5;
    const int n0   = blockIdx.x * NT;

    const int mw = wid & 7;       // row group (16 rows)
    const int nw = wid >> 3;      // col group (16 cols)
    const int g  = lane >> 2;     // 0..7
    const int tg = lane & 3;      // 0..3

    // ---- A fill: raw x window via 16B cp.async (4/thread, one group). ----
    {
        const unsigned as_u = (unsigned)__cvta_generic_to_shared(As);
        const int b = tid >> 3;
        const int q = tid & 7;
#pragma unroll
        for (int kc = 0; kc < 4; ++kc) {
            const int col = kc * 32 + q * 4;
            const int c = (n0 + col) & (CDIM - 1);
            asm volatile("cp.async.cg.shared.global [%0], [%1], 16;"
                         :: "r"(as_u + (unsigned)(b * ASTRIDE + col) * 4u),
                            "l"(x + (size_t)b * CDIM + c) : "memory");
        }
        asm volatile("cp.async.commit_group;" ::: "memory");
    }

    // ---- bias prefetch: thread's 4 consecutive output cols. ----
    const float4 bz = *(const float4*)(bias + n0 + nw * 16 + tg * 4);

    // ---- B fill: Bs[cl][perm(n)] = tf32(kernel[(n0+cl)%C][n0+n]) banded.
    //      perm within each 4-group: [c0, c2, c1, c3] = free y/z swap. ----
#pragma unroll
    for (int it = 0; it < 2; ++it) {
        const int idx = tid + it * THREADS;
        const int cl = idx >> 4;
        const int nb = (idx & 15) * 4;
        const int r  = (n0 + cl) & (CDIM - 1);
        const bool va = (cl >= nb) && (cl <= nb + 66);
        const float4 wv = va ? *(const float4*)(w + (size_t)r * NDIM + n0 + nb)
                             : make_float4(0.f, 0.f, 0.f, 0.f);
        uint4 st;   // slots hold cols nb, nb+2, nb+1, nb+3
        st.x = ((unsigned)(cl - nb)     < 64u) ? f2tf(wv.x) : 0u;
        st.y = ((unsigned)(cl - nb - 2) < 64u) ? f2tf(wv.z) : 0u;
        st.z = ((unsigned)(cl - nb - 1) < 64u) ? f2tf(wv.y) : 0u;
        st.w = ((unsigned)(cl - nb - 3) < 64u) ? f2tf(wv.w) : 0u;
        *(uint4*)&Bs[cl * BSTRIDE + nb] = st;
    }
    asm volatile("cp.async.wait_group 0;" ::: "memory");
    __syncthreads();   // the only barrier

    // ---- Mainloop: warp (mw, nw): rows mw*16..+15, cols nw*16..+15,
    //      k = 16nw .. 16nw+79 (band-trimmed, 10 unrolled k8-steps).
    //      B via LDS.64: phys pos 2g -> (col L_g, col H_g = L_g+2). ----
    float acc[2][4] = {{0.f, 0.f, 0.f, 0.f}, {0.f, 0.f, 0.f, 0.f}};

    const float*    Ap = As + (mw * 16 + g) * ASTRIDE + tg + nw * 16;
    const uint32_t* Bq = (const uint32_t*)Bs + (nw * 16 + tg) * BSTRIDE + nw * 16 + 2 * g;

#pragma unroll
    for (int s = 0; s < 10; ++s) {
        const int k0 = s * 8;
        const uint32_t a0 = __float_as_uint(Ap[k0]);                // raw bits = tf32 trunc
        const uint32_t a1 = __float_as_uint(Ap[8 * ASTRIDE + k0]);
        const uint32_t a2 = __float_as_uint(Ap[k0 + 4]);
        const uint32_t a3 = __float_as_uint(Ap[8 * ASTRIDE + k0 + 4]);
        const uint2 bl = *(const uint2*)(Bq + k0 * BSTRIDE);        // (b0, b2) row k0+tg
        const uint2 bh = *(const uint2*)(Bq + (k0 + 4) * BSTRIDE);  // (b1, b3) row k0+tg+4
        mma_tf32(acc[0], a0, a1, a2, a3, bl.x, bh.x);
        mma_tf32(acc[1], a0, a1, a2, a3, bl.y, bh.y);
    }

    // ---- Epilogue: 2x STG.128 (cols 4tg..4tg+3 consecutive) + bias. ----
    {
        const int row = mw * 16 + g;
        const int c0  = n0 + nw * 16 + tg * 4;
        float4 v0, v1;
        v0.x = acc[0][0] + bz.x;  v0.y = acc[0][1] + bz.y;
        v0.z = acc[1][0] + bz.z;  v0.w = acc[1][1] + bz.w;
        v1.x = acc[0][2] + bz.x;  v1.y = acc[0][3] + bz.y;
        v1.z = acc[1][2] + bz.z;  v1.w = acc[1][3] + bz.w;
        *(float4*)(out + (size_t)row * NDIM + c0)       = v0;
        *(float4*)(out + (size_t)(row + 8) * NDIM + c0) = v1;
    }
}

extern "C" void kernel_launch(void* const* d_in, const int* in_sizes, int n_in,
                              void* d_out, int out_size) {
    const float* x    = (const float*)d_in[0];
    const float* w    = (const float*)d_in[1];
    const float* bias = (const float*)d_in[2];
    float* out        = (float*)d_out;

    cudaFuncSetAttribute(cscfc_mma_kernel,
                         cudaFuncAttributeMaxDynamicSharedMemorySize, SMEM_NEED);
    cscfc_mma_kernel<<<NDIM / NT, THREADS, SMEM_NEED>>>(x, w, bias, out);
}

// round 15
// speedup vs baseline: 1.0036x; 1.0036x over previous
#include <cuda_runtime.h>
#include <cstdint>

// CSCFCLayer: out[b][n] = sum_{f<64} x[b][(n+f)%C] * kernel[(n+f)%C][n] + bias[n]
// B=128, C=N=8192, F=64, fp32.
//
// v15 = v11 skeleton (band-trimmed m16n8k8 tf32, grid 128, 1024 thr, direct-STG
// epilogue) with a fully-async fill:
//  - B fill via cp.async only (no LDG->STS register staging): per k-row the valid
//    band cols are contiguous; 16B chunks use src-size zero-fill for the tail,
//    unaligned heads (rows cl>=64) use <=3 4B cp.asyncs; Bs pre-zeroed.
//  - B stored raw fp32 -> tf32-truncated by HMMA (like A). No f2tf anywhere.
//  - A fill unchanged (4x 16B cp.async); single commit group covers A+B.

#define CDIM 8192
#define NDIM 8192
#define NT 64
#define THREADS 1024
#define ASTRIDE 132
#define BSTRIDE 72
#define A_FLOATS (128 * ASTRIDE)
#define B_FLOATS (128 * BSTRIDE)
#define SMEM_NEED ((A_FLOATS + B_FLOATS) * 4)

__device__ __forceinline__ void mma_tf32(float* c,
                                         uint32_t a0, uint32_t a1,
                                         uint32_t a2, uint32_t a3,
                                         uint32_t b0, uint32_t b1) {
    asm volatile(
        "mma.sync.aligned.m16n8k8.row.col.f32.tf32.tf32.f32 "
        "{%0,%1,%2,%3}, {%4,%5,%6,%7}, {%8,%9}, {%0,%1,%2,%3};"
        : "+f"(c[0]), "+f"(c[1]), "+f"(c[2]), "+f"(c[3])
        : "r"(a0), "r"(a1), "r"(a2), "r"(a3), "r"(b0), "r"(b1));
}

extern "C" __global__ void __launch_bounds__(THREADS, 1)
cscfc_mma_kernel(const float* __restrict__ x,
                 const float* __restrict__ w,
                 const float* __restrict__ bias,
                 float* __restrict__ out)
{
    extern __shared__ float sm[];
    float* As = sm;               // [128 b][ASTRIDE] raw fp32 x window
    float* Bs = sm + A_FLOATS;    // [128 k][BSTRIDE] raw fp32 banded weights [k][n]

    const int tid  = threadIdx.x;
    const int lane = tid & 31;
    const int wid  = tid >> 5;
    const int n0   = blockIdx.x * NT;

    const int mw = wid & 7;       // row group (16 rows)
    const int nw = wid >> 3;      // col group (16 cols)
    const int g  = lane >> 2;     // 0..7
    const int tg = lane & 3;      // 0..3

    const unsigned as_u = (unsigned)__cvta_generic_to_shared(As);
    const unsigned bs_u = (unsigned)__cvta_generic_to_shared(Bs);

    // ---- A fill: raw x window via 16B cp.async (4/thread). ----
    {
        const int b = tid >> 3;
        const int q = tid & 7;
#pragma unroll
        for (int kc = 0; kc < 4; ++kc) {
            const int col = kc * 32 + q * 4;
            const int c = (n0 + col) & (CDIM - 1);
            asm volatile("cp.async.cg.shared.global [%0], [%1], 16;"
                         :: "r"(as_u + (unsigned)(b * ASTRIDE + col) * 4u),
                            "l"(x + (size_t)b * CDIM + c) : "memory");
        }
    }

    // ---- Pre-zero Bs (covers band-external slots not written below). ----
#pragma unroll
    for (int i = tid; i < B_FLOATS / 4; i += THREADS)
        ((float4*)Bs)[i] = make_float4(0.f, 0.f, 0.f, 0.f);

    // ---- bias prefetch. ----
    const float2 bz0 = *(const float2*)(bias + n0 + nw * 16 + tg * 2);
    const float2 bz1 = *(const float2*)(bias + n0 + nw * 16 + 8 + tg * 2);

    __syncthreads();   // zero-stores complete before async B writes land

    // ---- B fill, pure cp.async: row cl valid cols [lo, hi] contiguous.
    //      8 threads/row; thread j handles 16B slots j and j+8.
    //      Full/tail slots: one 16B cp.async with src-size zero-fill.
    //      Head slot (unaligned lo): <=3 4B cp.asyncs. ----
    {
        const int cl = tid >> 3;           // 0..127
        const int j  = tid & 7;
        const int r  = (n0 + cl) & (CDIM - 1);
        const float* wr = w + (size_t)r * NDIM + n0;
        const int lo = (cl - 63 > 0) ? cl - 63 : 0;
        const int hi = (cl < 63) ? cl : 63;
        const unsigned brow = bs_u + (unsigned)(cl * BSTRIDE) * 4u;
#pragma unroll
        for (int t = 0; t < 2; ++t) {
            const int s  = j + t * 8;      // slot 0..15
            const int sl = s * 4;
            const int sr = sl + 3;
            if (sl > hi || sr < lo) continue;          // outside band (pre-zeroed)
            if (sl >= lo) {
                const int he = (sr < hi) ? sr : hi;
                const unsigned bytes = (unsigned)(he - sl + 1) * 4u;  // 4..16
                asm volatile("cp.async.ca.shared.global [%0], [%1], 16, %2;"
                             :: "r"(brow + (unsigned)sl * 4u),
                                "l"(wr + sl), "r"(bytes) : "memory");
            } else {
                const int he = (sr < hi) ? sr : hi;
                for (int n = lo; n <= he; ++n)
                    asm volatile("cp.async.ca.shared.global [%0], [%1], 4;"
                                 :: "r"(brow + (unsigned)n * 4u),
                                    "l"(wr + n) : "memory");
            }
        }
    }
    asm volatile("cp.async.commit_group;" ::: "memory");
    asm volatile("cp.async.wait_group 0;" ::: "memory");
    __syncthreads();

    // ---- Mainloop: warp (mw, nw): rows mw*16..+15, cols nw*16..+15,
    //      k = 16nw .. 16nw+79 (band-trimmed, 10 unrolled k8-steps).
    //      Both A and B raw fp32 bits -> tf32 truncation in HMMA. ----
    float acc[2][4] = {{0.f, 0.f, 0.f, 0.f}, {0.f, 0.f, 0.f, 0.f}};

    const float*    Ap = As + (mw * 16 + g) * ASTRIDE + tg + nw * 16;
    const uint32_t* Bq = (const uint32_t*)Bs + (nw * 16 + tg) * BSTRIDE + nw * 16 + g;

#pragma unroll
    for (int s = 0; s < 10; ++s) {
        const int k0 = s * 8;
        const uint32_t a0 = __float_as_uint(Ap[k0]);
        const uint32_t a1 = __float_as_uint(Ap[8 * ASTRIDE + k0]);
        const uint32_t a2 = __float_as_uint(Ap[k0 + 4]);
        const uint32_t a3 = __float_as_uint(Ap[8 * ASTRIDE + k0 + 4]);
        const uint32_t b0 = Bq[k0 * BSTRIDE];
        const uint32_t b1 = Bq[(k0 + 4) * BSTRIDE];
        const uint32_t b2 = Bq[k0 * BSTRIDE + 8];
        const uint32_t b3 = Bq[(k0 + 4) * BSTRIDE + 8];
        mma_tf32(acc[0], a0, a1, a2, a3, b0, b1);
        mma_tf32(acc[1], a0, a1, a2, a3, b2, b3);
    }

    // ---- Epilogue: direct STG.64 + bias. ----
    {
        const int row = mw * 16 + g;
        const int c0  = n0 + nw * 16 + tg * 2;
        float* o0 = out + (size_t)row * NDIM + c0;
        float* o1 = out + (size_t)(row + 8) * NDIM + c0;
        *(float2*)o0       = make_float2(acc[0][0] + bz0.x, acc[0][1] + bz0.y);
        *(float2*)o1       = make_float2(acc[0][2] + bz0.x, acc[0][3] + bz0.y);
        *(float2*)(o0 + 8) = make_float2(acc[1][0] + bz1.x, acc[1][1] + bz1.y);
        *(float2*)(o1 + 8) = make_float2(acc[1][2] + bz1.x, acc[1][3] + bz1.y);
    }
}

extern "C" void kernel_launch(void* const* d_in, const int* in_sizes, int n_in,
                              void* d_out, int out_size) {
    const float* x    = (const float*)d_in[0];
    const float* w    = (const float*)d_in[1];
    const float* bias = (const float*)d_in[2];
    float* out        = (float*)d_out;

    cudaFuncSetAttribute(cscfc_mma_kernel,
                         cudaFuncAttributeMaxDynamicSharedMemorySize, SMEM_NEED);
    cscfc_mma_kernel<<<NDIM / NT, THREADS, SMEM_NEED>>>(x, w, bias, out);
}